// round 15
// baseline (speedup 1.0000x reference)
#include <cuda_runtime.h>
#include <cfloat>

// Problem shapes are FIXED by the reference (CAPACITY = 2^21, SIZE = 2^20).
#define CAP   2097152
#define NSAMP 1048576
#define DEPTH 21

// 1-BASED sum tree, INTERNAL NODES ONLY: node q at g_tree[q], children 2q/2q+1,
// level L at [2^L, 2^(L+1)), L = 0..20. Leaf level (21) is NOT stored:
// leaf l in [2^21, 2^22) is pri[l - CAP]. 8 MB static scratch.
__device__ float g_tree[CAP];
// Exclusive prefix of the 4096 level-12 node sums; g_pref[4096] = sentinel.
__device__ float g_pref[4097];
__device__ unsigned g_ctr;

// ---------------------------------------------------------------------------
// Fused build: 256 thr/block, 8 leaves/thread. Levels 20/19/18 in registers
// (vector stores), 17..13 warp shuffles, 12..10 by warp 0. Last block
// (atomic ticket) reduces levels 9..0 AND emits the level-12 prefix scan.
// All tree sums adjacent pairs -> bit-identical to jnp reshape(-1,2).sum.
// ---------------------------------------------------------------------------
__global__ __launch_bounds__(256) void build_tree(const float* __restrict__ pri) {
    __shared__ float swarp[8];
    const int t   = threadIdx.x;
    const int b   = blockIdx.x;
    const int lid = t & 31;
    const int w   = t >> 5;
    const int g   = b * 256 + t;          // 0 .. 2^18-1

    const float4* p4 = reinterpret_cast<const float4*>(pri);
    const float4 a = p4[2 * g];
    const float4 c = p4[2 * g + 1];

    const float s0 = a.x + a.y, s1 = a.z + a.w;
    const float s2 = c.x + c.y, s3 = c.z + c.w;
    *reinterpret_cast<float4*>(&g_tree[(1 << 20) + 4 * g]) =
        make_float4(s0, s1, s2, s3);

    const float t0 = s0 + s1, t1 = s2 + s3;
    *reinterpret_cast<float2*>(&g_tree[(1 << 19) + 2 * g]) =
        make_float2(t0, t1);

    float val = t0 + t1;
    g_tree[(1 << 18) + g] = val;

    const int wg = b * 8 + w;
    #pragma unroll
    for (int L = 17, n = 16; L >= 13; L--, n >>= 1) {
        const float pair = val + __shfl_down_sync(0xffffffffu, val, 1);
        val = __shfl_sync(0xffffffffu, pair, 2 * lid);
        if (lid < n) g_tree[(1 << L) + wg * n + lid] = val;
    }

    if (lid == 0) swarp[w] = val;
    __syncthreads();
    if (w == 0) {
        float x = (lid < 8) ? swarp[lid] : 0.0f;
        #pragma unroll
        for (int L = 12, n = 4; L >= 10; L--, n >>= 1) {
            const float pair = x + __shfl_down_sync(0xffffffffu, x, 1);
            x = __shfl_sync(0xffffffffu, pair, 2 * lid);
            if (lid < n) g_tree[(1 << L) + b * n + lid] = x;
        }
    }

    // ---- last-block fusion ---------------------------------------------
    __threadfence();
    __syncthreads();
    __shared__ unsigned rank;
    if (t == 0) rank = atomicAdd(&g_ctr, 1u);
    __syncthreads();
    if (rank != gridDim.x - 1) return;
    if (t == 0) g_ctr = 0;                // self-reset: graph-replay safe
    __threadfence();

    // levels 9..0
    __shared__ float sb[1024];
    #pragma unroll
    for (int k = 0; k < 4; k++)
        sb[t + 256 * k] = g_tree[(1 << 10) + t + 256 * k];
    __syncthreads();

    int level = 9;
    for (int n = 512; n >= 1; n >>= 1, level--) {
        float x0 = 0.0f, x1 = 0.0f;
        if (t < n)        x0 = sb[2 * t] + sb[2 * t + 1];
        if (t + 256 < n)  x1 = sb[2 * (t + 256)] + sb[2 * (t + 256) + 1];
        __syncthreads();
        if (t < n)       { sb[t] = x0;       g_tree[(1 << level) + t] = x0; }
        if (t + 256 < n) { sb[t + 256] = x1; g_tree[(1 << level) + t + 256] = x1; }
        __syncthreads();
    }
    __syncthreads();

    // exclusive prefix of level 12 (g_tree[4096..8191]) -> g_pref[0..4095]
    {
        float loc[16];
        float run = 0.0f;
        #pragma unroll
        for (int k = 0; k < 16; k++) {
            loc[k] = run;                              // exclusive within chunk
            run += g_tree[4096 + t * 16 + k];
        }
        // inclusive warp scan of chunk totals
        float x = run;
        #pragma unroll
        for (int o = 1; o < 32; o <<= 1) {
            const float y = __shfl_up_sync(0xffffffffu, x, o);
            if (lid >= o) x += y;
        }
        __shared__ float wsum[8];
        if (lid == 31) wsum[w] = x;
        __syncthreads();
        __shared__ float wbase[8];
        if (t == 0) {
            float acc = 0.0f;
            #pragma unroll
            for (int i = 0; i < 8; i++) { wbase[i] = acc; acc += wsum[i]; }
        }
        __syncthreads();
        const float base = wbase[w] + (x - run);       // exclusive thread base
        #pragma unroll
        for (int k = 0; k < 16; k++)
            g_pref[t * 16 + k] = base + loc[k];
        if (t == 255) g_pref[4096] = FLT_MAX;          // sentinel
    }
}

// ---------------------------------------------------------------------------
// Traversal with LEVEL-12 JUMP-START, blocked ILP=4.
// Stratified samples: the level-12 node index is ~ s*4096/total +- ~1
// (Brownian-bridge bound), so a guess + short local scan on the 16 KB
// L1-resident prefix replaces the top 12 descent steps. Then descend
// levels 12..20 (8 internal loads) + leaf from pri. Output float32.
// ---------------------------------------------------------------------------
#define TRAV_BLK 256
#define ILP      4

__global__ __launch_bounds__(TRAV_BLK) void traverse(const float* __restrict__ uni,
                                                     const float* __restrict__ pri,
                                                     float* __restrict__ out) {
    const int j = blockIdx.x * TRAV_BLK + threadIdx.x;   // 0 .. NSAMP/4-1

    const float total = __ldg(&g_tree[1]);
    const float step  = total / (float)NSAMP;
    const float inv12 = 4096.0f / total;
    const float4 u = reinterpret_cast<const float4*>(uni)[j];

    float s[ILP];
    int   idx[ILP];
    s[0] = (u.x + (float)(4 * j + 0)) * step;
    s[1] = (u.y + (float)(4 * j + 1)) * step;
    s[2] = (u.z + (float)(4 * j + 2)) * step;
    s[3] = (u.w + (float)(4 * j + 3)) * step;

    // ---- jump-start: locate level-12 node via guess + local scan --------
    #pragma unroll
    for (int k = 0; k < ILP; k++) {
        int q = (int)(s[k] * inv12);
        q = max(0, min(4095, q));
        // want: pref[q] < s <= pref[q+1]   (matches "go left if s <= left")
        while (q > 0 && __ldg(&g_pref[q]) >= s[k]) q--;
        while (__ldg(&g_pref[q + 1]) < s[k]) q++;   // sentinel caps at 4095
        s[k] -= __ldg(&g_pref[q]);
        idx[k] = 4096 + q;                           // 1-based node, level 12
    }

    // ---- descend levels 12..19 (children in g_tree, levels 13..20) ------
    #pragma unroll
    for (int d = 12; d < DEPTH - 1; d++) {
        #pragma unroll
        for (int k = 0; k < ILP; k++) {
            const int l = 2 * idx[k];
            const float v = __ldg(&g_tree[l]);
            if (s[k] <= v) { idx[k] = l; } else { idx[k] = l + 1; s[k] -= v; }
        }
    }

    // ---- step 20: leaves live in pri (leaf l -> pri[l - CAP]) -----------
    float4 r;
    {
        const int l0 = 2 * idx[0], l1 = 2 * idx[1];
        const int l2 = 2 * idx[2], l3 = 2 * idx[3];
        const float v0 = __ldg(&pri[l0 - CAP]);
        const float v1 = __ldg(&pri[l1 - CAP]);
        const float v2 = __ldg(&pri[l2 - CAP]);
        const float v3 = __ldg(&pri[l3 - CAP]);
        r.x = (float)((s[0] <= v0 ? l0 : l0 + 1) - CAP);
        r.y = (float)((s[1] <= v1 ? l1 : l1 + 1) - CAP);
        r.z = (float)((s[2] <= v2 ? l2 : l2 + 1) - CAP);
        r.w = (float)((s[3] <= v3 ? l3 : l3 + 1) - CAP);
    }
    reinterpret_cast<float4*>(out)[j] = r;
}

extern "C" void kernel_launch(void* const* d_in, const int* in_sizes, int n_in,
                              void* d_out, int out_size) {
    const float* pri = (const float*)d_in[0];
    const float* uni = (const float*)d_in[1];
    if (n_in >= 2 && in_sizes[1] == 2 * in_sizes[0]) {
        pri = (const float*)d_in[1];
        uni = (const float*)d_in[0];
    }

    build_tree<<<1024, 256>>>(pri);                  // levels 20..0 + prefix12

    traverse<<<NSAMP / ILP / TRAV_BLK, TRAV_BLK>>>(uni, pri, (float*)d_out);
}

// round 16
// speedup vs baseline: 1.0451x; 1.0451x over previous
#include <cuda_runtime.h>
#include <cfloat>

// Problem shapes are FIXED by the reference (CAPACITY = 2^21, SIZE = 2^20).
#define CAP   2097152
#define NSAMP 1048576
#define DEPTH 21

// 1-BASED sum tree, PARTIAL: only levels 13..20 are materialized
// (node q at g_tree[q], children 2q/2q+1; level L at [2^L, 2^(L+1))).
// Leaves (level 21): pri[l - CAP]. Levels 0..11 are never needed —
// the traversal jump-starts at level 12 via g_pref. g_tree[1] holds the total.
__device__ float g_tree[CAP];
// Exclusive prefix of the 4096 level-12 node sums; g_pref[4096] = sentinel.
__device__ float g_pref[4097];

// ---------------------------------------------------------------------------
// Build levels 20..13: 256 thr/block, 8 leaves/thread (two float4 loads).
// Levels 20/19/18 in registers (vector stores), 17..13 via warp shuffles
// (level 13 = 1 node per warp). NO barriers, NO atomics, NO inter-block sync.
// All sums adjacent pairs -> bit-identical to jnp reshape(-1,2).sum.
// ---------------------------------------------------------------------------
__global__ __launch_bounds__(256) void build_tree(const float* __restrict__ pri) {
    const int t   = threadIdx.x;
    const int b   = blockIdx.x;
    const int lid = t & 31;
    const int w   = t >> 5;
    const int g   = b * 256 + t;          // 0 .. 2^18-1

    const float4* p4 = reinterpret_cast<const float4*>(pri);
    const float4 a = p4[2 * g];
    const float4 c = p4[2 * g + 1];

    const float s0 = a.x + a.y, s1 = a.z + a.w;
    const float s2 = c.x + c.y, s3 = c.z + c.w;
    *reinterpret_cast<float4*>(&g_tree[(1 << 20) + 4 * g]) =
        make_float4(s0, s1, s2, s3);

    const float t0 = s0 + s1, t1 = s2 + s3;
    *reinterpret_cast<float2*>(&g_tree[(1 << 19) + 2 * g]) =
        make_float2(t0, t1);

    float val = t0 + t1;
    g_tree[(1 << 18) + g] = val;

    const int wg = b * 8 + w;             // global warp id = level-13 node id
    #pragma unroll
    for (int L = 17, n = 16; L >= 13; L--, n >>= 1) {
        const float pair = val + __shfl_down_sync(0xffffffffu, val, 1);
        val = __shfl_sync(0xffffffffu, pair, 2 * lid);
        if (lid < n) g_tree[(1 << L) + wg * n + lid] = val;
    }
}

// ---------------------------------------------------------------------------
// Level-12 prefix: one block, 256 threads. Level-12 node n = sum of level-13
// pair (adjacent-pair order preserved). Each thread handles 16 nodes
// (32 consecutive level-13 floats, 8x float4). Exclusive block scan ->
// g_pref[0..4095]; sentinel at [4096]; grand total -> g_tree[1].
// ---------------------------------------------------------------------------
__global__ __launch_bounds__(256) void prefix12() {
    const int t   = threadIdx.x;
    const int lid = t & 31;
    const int w   = t >> 5;

    // 16 level-12 sums from 32 level-13 values
    const float4* l13 = reinterpret_cast<const float4*>(&g_tree[1 << 13]);
    float loc[16];
    float run = 0.0f;
    #pragma unroll
    for (int k = 0; k < 8; k++) {
        const float4 v = l13[t * 8 + k];
        loc[2 * k]     = run;  run += v.x + v.y;
        loc[2 * k + 1] = run;  run += v.z + v.w;
    }

    // inclusive warp scan of per-thread totals
    float x = run;
    #pragma unroll
    for (int o = 1; o < 32; o <<= 1) {
        const float y = __shfl_up_sync(0xffffffffu, x, o);
        if (lid >= o) x += y;
    }
    __shared__ float wsum[8], wbase[8];
    if (lid == 31) wsum[w] = x;
    __syncthreads();
    if (t == 0) {
        float acc = 0.0f;
        #pragma unroll
        for (int i = 0; i < 8; i++) { wbase[i] = acc; acc += wsum[i]; }
        g_tree[1] = acc;                  // total
        g_pref[4096] = FLT_MAX;           // sentinel
    }
    __syncthreads();

    const float base = wbase[w] + (x - run);   // exclusive thread base
    #pragma unroll
    for (int k = 0; k < 16; k++)
        g_pref[t * 16 + k] = base + loc[k];
}

// ---------------------------------------------------------------------------
// Traversal with LEVEL-12 JUMP-START, blocked ILP=4 (thread j walks samples
// 4j..4j+3; adjacent chains share cache lines at every level). Guess
// q = s*4096/total, fix with a short local scan on the 16 KB L1-resident
// prefix, then descend levels 12..20 (8 loads) + leaf from pri.
// Output float32 (validator dtype); values < 2^21 exact.
// ---------------------------------------------------------------------------
#define TRAV_BLK 256
#define ILP      4

__global__ __launch_bounds__(TRAV_BLK) void traverse(const float* __restrict__ uni,
                                                     const float* __restrict__ pri,
                                                     float* __restrict__ out) {
    const int j = blockIdx.x * TRAV_BLK + threadIdx.x;   // 0 .. NSAMP/4-1

    const float total = __ldg(&g_tree[1]);
    const float step  = total / (float)NSAMP;
    const float inv12 = 4096.0f / total;
    const float4 u = reinterpret_cast<const float4*>(uni)[j];

    float s[ILP];
    int   idx[ILP];
    s[0] = (u.x + (float)(4 * j + 0)) * step;
    s[1] = (u.y + (float)(4 * j + 1)) * step;
    s[2] = (u.z + (float)(4 * j + 2)) * step;
    s[3] = (u.w + (float)(4 * j + 3)) * step;

    // jump-start: locate level-12 node via guess + local scan
    #pragma unroll
    for (int k = 0; k < ILP; k++) {
        int q = (int)(s[k] * inv12);
        q = max(0, min(4095, q));
        while (q > 0 && __ldg(&g_pref[q]) >= s[k]) q--;
        while (__ldg(&g_pref[q + 1]) < s[k]) q++;    // sentinel caps at 4095
        s[k] -= __ldg(&g_pref[q]);
        idx[k] = 4096 + q;                            // 1-based node, level 12
    }

    // descend levels 12..19 (children at levels 13..20 in g_tree)
    #pragma unroll
    for (int d = 12; d < DEPTH - 1; d++) {
        #pragma unroll
        for (int k = 0; k < ILP; k++) {
            const int l = 2 * idx[k];
            const float v = __ldg(&g_tree[l]);
            if (s[k] <= v) { idx[k] = l; } else { idx[k] = l + 1; s[k] -= v; }
        }
    }

    // final step: leaves live in pri (leaf l -> pri[l - CAP])
    float4 r;
    {
        const int l0 = 2 * idx[0], l1 = 2 * idx[1];
        const int l2 = 2 * idx[2], l3 = 2 * idx[3];
        const float v0 = __ldg(&pri[l0 - CAP]);
        const float v1 = __ldg(&pri[l1 - CAP]);
        const float v2 = __ldg(&pri[l2 - CAP]);
        const float v3 = __ldg(&pri[l3 - CAP]);
        r.x = (float)((s[0] <= v0 ? l0 : l0 + 1) - CAP);
        r.y = (float)((s[1] <= v1 ? l1 : l1 + 1) - CAP);
        r.z = (float)((s[2] <= v2 ? l2 : l2 + 1) - CAP);
        r.w = (float)((s[3] <= v3 ? l3 : l3 + 1) - CAP);
    }
    reinterpret_cast<float4*>(out)[j] = r;
}

extern "C" void kernel_launch(void* const* d_in, const int* in_sizes, int n_in,
                              void* d_out, int out_size) {
    const float* pri = (const float*)d_in[0];
    const float* uni = (const float*)d_in[1];
    if (n_in >= 2 && in_sizes[1] == 2 * in_sizes[0]) {
        pri = (const float*)d_in[1];
        uni = (const float*)d_in[0];
    }

    build_tree<<<1024, 256>>>(pri);   // levels 20..13 only, barrier-free
    prefix12<<<1, 256>>>();           // level-12 prefix + total

    traverse<<<NSAMP / ILP / TRAV_BLK, TRAV_BLK>>>(uni, pri, (float*)d_out);
}